// round 9
// baseline (speedup 1.0000x reference)
#include <cuda_runtime.h>
#include <cuda_bf16.h>

// BuzzLoss: B=8192 rows, T=1024 cols.
// ONE WARP PER ROW, autonomous. Lane l owns elements {j*128 + 4l + e}.
// R8 algorithm, but with __launch_bounds__(256, 4) to give ptxas a 64-reg
// budget so the 16 coalesced LDG.128 are genuinely front-batched (R7/R8
// compiled to 32 regs and sank the loads -> only ~2 outstanding per warp).
// Load phase: 8 c-loads then 8 a-loads, compiler barrier, then per-segment
// reduction to (p, s1loc, s2loc); phase 2 is register/shfl math only.

#define FULL_MASK 0xFFFFFFFFu
#define ROWS_PER_CTA 8

__global__ void buzz_zero_kernel(float* out) {
    out[0] = 0.0f;
}

__global__ __launch_bounds__(256, 4)
void buzz_loss_kernel(const float* __restrict__ conf,
                      const float* __restrict__ acc,
                      float* __restrict__ out,
                      float negInvB) {
    const int tid  = threadIdx.x;
    const int lane = tid & 31;
    const int wid  = tid >> 5;
    const size_t row = (size_t)blockIdx.x * ROWS_PER_CTA + wid;

    __shared__ float s_total;
    if (tid == 0) s_total = 0.0f;
    __syncthreads();

    const float4* c4 = reinterpret_cast<const float4*>(conf + row * 1024) + lane;
    const float4* a4 = reinterpret_cast<const float4*>(acc  + row * 1024) + lane;

    // ---- Phase 1: front-batched loads (16 independent LDG.128) ----
    float4 c[8], a[8];
    #pragma unroll
    for (int j = 0; j < 8; j++) c[j] = __ldg(&c4[j * 32]);
    #pragma unroll
    for (int j = 0; j < 8; j++) a[j] = __ldg(&a4[j * 32]);
    asm volatile("" ::: "memory");

    // Per-segment reduction; c/a die here.
    float p[8], s1loc[8], s2loc[8];
    #pragma unroll
    for (int j = 0; j < 8; j++) {
        const float q0 = 1.0f - c[j].x;
        const float q1 = 1.0f - c[j].y;
        const float q2 = 1.0f - c[j].z;
        const float q3 = 1.0f - c[j].w;

        const float lb0 = c[j].x;
        const float lb1 = c[j].y * q0;
        const float lb2 = c[j].z * (q0 * q1);
        const float lb3 = c[j].w * (q0 * q1 * q2);

        p[j] = (q0 * q1) * (q2 * q3);
        s1loc[j] = fmaf(lb0, a[j].x, fmaf(lb1, a[j].y,
                   fmaf(lb2, a[j].z, lb3 * a[j].w)));
        s2loc[j] = (lb0 + lb1) + (lb2 + lb3);
    }
    const float lastA = a[7].w;          // lane 31 -> acc[row, 1023]

    // ---- Phase 2: 8 interleaved warp product-scans ----
    #pragma unroll
    for (int d = 1; d < 32; d <<= 1) {
        #pragma unroll
        for (int j = 0; j < 8; j++) {
            float v = __shfl_up_sync(FULL_MASK, p[j], d);
            if (lane >= d) p[j] *= v;
        }
    }

    float tot[8], E[8];
    #pragma unroll
    for (int j = 0; j < 8; j++) {
        tot[j] = __shfl_sync(FULL_MASK, p[j], 31);
        E[j]   = __shfl_up_sync(FULL_MASK, p[j], 1);
        if (lane == 0) E[j] = 1.0f;
    }

    // Serial cross-segment chain (8 FMULs deep)
    float R = 1.0f, s1 = 0.0f, s2 = 0.0f;
    #pragma unroll
    for (int j = 0; j < 8; j++) {
        const float Ej = E[j] * R;
        s1 = fmaf(Ej, s1loc[j], s1);
        s2 = fmaf(Ej, s2loc[j], s2);
        R *= tot[j];
    }

    // Warp reduce
    #pragma unroll
    for (int d = 16; d >= 1; d >>= 1) {
        s1 += __shfl_down_sync(FULL_MASK, s1, d);
        s2 += __shfl_down_sync(FULL_MASK, s2, d);
    }
    const float accLast = __shfl_sync(FULL_MASK, lastA, 31);

    if (lane == 0) {
        const float score = s1 + (1.0f - s2) * accLast;
        atomicAdd(&s_total, score);
    }

    __syncthreads();
    if (tid == 0) {
        atomicAdd(out, s_total * negInvB);
    }
}

extern "C" void kernel_launch(void* const* d_in, const int* in_sizes, int n_in,
                              void* d_out, int out_size) {
    const float* conf = (const float*)d_in[0];
    const float* acc  = (const float*)d_in[1];
    float* out = (float*)d_out;

    const int total = in_sizes[0];
    const int T = 1024;
    const int B = total / T;

    buzz_zero_kernel<<<1, 1>>>(out);
    buzz_loss_kernel<<<B / ROWS_PER_CTA, 256>>>(conf, acc, out,
                                                -1.0f / (float)B);
}